// round 1
// baseline (speedup 1.0000x reference)
#include <cuda_runtime.h>

#define NF 128                  // in/out features
#define ED 16                   // edge attr dim
#define NB 16                   // batch
#define SB 1024                 // nodes per batch (S)
#define EB 8192                 // edges per batch (E)
#define NN (NB*SB)              // 16384 total nodes
#define BE (NB*EB)              // 131072 directed input edges
#define MM (2*BE + NN)          // 278528 total edges incl. reverse + self loops

// ---- scratch (device globals; no allocation allowed) ----
__device__ float    g_xt[(size_t)NN*NF];   // x @ W          (8 MB)
__device__ float    g_s1[NN];
__device__ float    g_s2[NN];
__device__ float    g_e[MM];               // per-edge logits (1.1 MB)
__device__ unsigned g_maxk[NN];            // order-encoded segment max
__device__ float    g_denom[NN];

// order-preserving float <-> uint encoding for atomicMax
__device__ __forceinline__ unsigned fenc(float f){
    unsigned u = __float_as_uint(f);
    return (u & 0x80000000u) ? ~u : (u | 0x80000000u);
}
__device__ __forceinline__ float fdec(unsigned k){
    return __uint_as_float((k & 0x80000000u) ? (k & 0x7fffffffu) : ~k);
}

// ---- K0: zero output accumulator + denom + max keys ----
__global__ void k_init(float* __restrict__ out){
    int i = blockIdx.x*blockDim.x + threadIdx.x;
    if (i < NN*NF) out[i] = 0.f;
    if (i < NN){ g_denom[i] = 0.f; g_maxk[i] = 0u; }
}

// ---- K1: xt = x @ W. 64-row tiles, 256 threads, 4x8 register micro-tile ----
__global__ __launch_bounds__(256) void k_gemm(const float* __restrict__ x,
                                              const float* __restrict__ W){
    extern __shared__ float sm[];
    float* Wsm = sm;              // [128][128]
    float* Xsm = sm + NF*NF;      // [128][68]  k-major (transposed x tile), padded
    const int XS = 68;
    int tid  = threadIdx.x;
    int row0 = blockIdx.x * 64;

    // stage W (16384 floats)
    const float4* W4 = (const float4*)W;
    float4* Wsm4 = (float4*)Wsm;
    #pragma unroll
    for (int i = tid; i < NF*NF/4; i += 256) Wsm4[i] = W4[i];

    // stage x tile transposed: Xsm[k][r]
    for (int i = tid; i < 64*32; i += 256){
        int r = i >> 5, c4 = (i & 31) << 2;
        float4 v = ((const float4*)(x + (size_t)(row0 + r)*NF))[i & 31];
        Xsm[(c4+0)*XS + r] = v.x;
        Xsm[(c4+1)*XS + r] = v.y;
        Xsm[(c4+2)*XS + r] = v.z;
        Xsm[(c4+3)*XS + r] = v.w;
    }
    __syncthreads();

    int tx = tid & 15;      // col group: cols 8*tx..8*tx+7
    int ty = tid >> 4;      // row group: rows 4*ty..4*ty+3
    float acc[4][8];
    #pragma unroll
    for (int i = 0; i < 4; i++)
        #pragma unroll
        for (int j = 0; j < 8; j++) acc[i][j] = 0.f;

    #pragma unroll 4
    for (int k = 0; k < NF; k++){
        float4 xv = *(const float4*)&Xsm[k*XS + 4*ty];
        float4 w0 = *(const float4*)&Wsm[k*NF + 8*tx];
        float4 w1 = *(const float4*)&Wsm[k*NF + 8*tx + 4];
        float xr[4] = {xv.x, xv.y, xv.z, xv.w};
        float wr[8] = {w0.x, w0.y, w0.z, w0.w, w1.x, w1.y, w1.z, w1.w};
        #pragma unroll
        for (int i = 0; i < 4; i++)
            #pragma unroll
            for (int j = 0; j < 8; j++)
                acc[i][j] = fmaf(xr[i], wr[j], acc[i][j]);
    }

    #pragma unroll
    for (int i = 0; i < 4; i++){
        size_t r = (size_t)(row0 + 4*ty + i);
        float4 o0 = {acc[i][0], acc[i][1], acc[i][2], acc[i][3]};
        float4 o1 = {acc[i][4], acc[i][5], acc[i][6], acc[i][7]};
        float4* p = (float4*)(g_xt + r*NF);
        p[2*tx]   = o0;
        p[2*tx+1] = o1;
    }
}

// ---- K1b: s1[n] = xt[n]·a[0:128], s2[n] = xt[n]·a[128:256]. warp per node ----
__global__ void k_proj(const float* __restrict__ a){
    int n = blockIdx.x*4 + (threadIdx.x >> 5);
    int l = threadIdx.x & 31;
    float4 v  = ((const float4*)(g_xt + (size_t)n*NF))[l];
    float4 a1 = __ldg(&((const float4*)a)[l]);
    float4 a2 = __ldg(&((const float4*)(a + NF))[l]);
    float p1 = v.x*a1.x + v.y*a1.y + v.z*a1.z + v.w*a1.w;
    float p2 = v.x*a2.x + v.y*a2.y + v.z*a2.z + v.w*a2.w;
    #pragma unroll
    for (int o = 16; o; o >>= 1){
        p1 += __shfl_xor_sync(0xffffffffu, p1, o);
        p2 += __shfl_xor_sync(0xffffffffu, p2, o);
    }
    if (!l){ g_s1[n] = p1; g_s2[n] = p2; }
}

// ---- K2: per-edge logit + segment max ----
__global__ void k_logits(const int* __restrict__ ei, const float* __restrict__ ea,
                         const float* __restrict__ a){
    int m = blockIdx.x*blockDim.x + threadIdx.x;
    if (m >= MM) return;
    int src, dst;
    float t = 0.f;
    if (m < 2*BE){
        int i    = (m < BE) ? m : m - BE;
        int base = (i >> 13) << 10;              // (i/E)*S  (E=8192, S=1024)
        int u = __ldg(&ei[2*i])   + base;
        int v = __ldg(&ei[2*i+1]) + base;
        src = (m < BE) ? u : v;
        dst = (m < BE) ? v : u;
        const float4* e4 = (const float4*)(ea + (size_t)i*ED);
        const float4* a3 = (const float4*)(a + 2*NF);
        #pragma unroll
        for (int d = 0; d < 4; d++){
            float4 ev = __ldg(&e4[d]);
            float4 av = __ldg(&a3[d]);
            t += ev.x*av.x + ev.y*av.y + ev.z*av.z + ev.w*av.w;
        }
    } else {
        src = dst = m - 2*BE;                    // self loop, zero edge attr
    }
    t += __ldg(&g_s1[src]) + __ldg(&g_s2[dst]);
    float e = (t > 0.f) ? t : 0.2f*t;            // leaky_relu, T=1
    g_e[m] = e;
    atomicMax(&g_maxk[dst], fenc(e));
}

// ---- K3: warp per edge: ex = exp(e - max[dst]); denom += ex; out[dst] += ex*xt[src]
__global__ __launch_bounds__(256) void k_scatter(const int* __restrict__ ei,
                                                 float* __restrict__ out){
    int m = (int)((blockIdx.x*blockDim.x + threadIdx.x) >> 5);
    int l = threadIdx.x & 31;
    if (m >= MM) return;
    int src, dst;
    if (m < 2*BE){
        int i    = (m < BE) ? m : m - BE;
        int base = (i >> 13) << 10;
        int u = __ldg(&ei[2*i])   + base;
        int v = __ldg(&ei[2*i+1]) + base;
        src = (m < BE) ? u : v;
        dst = (m < BE) ? v : u;
    } else {
        src = dst = m - 2*BE;
    }
    float ex = expf(g_e[m] - fdec(g_maxk[dst]));
    if (!l) atomicAdd(&g_denom[dst], ex);
    float4 v = __ldg(&((const float4*)(g_xt + (size_t)src*NF))[l]);
    float* po = out + (size_t)dst*NF + 4*l;
    asm volatile("red.global.add.v4.f32 [%0], {%1,%2,%3,%4};"
        :: "l"(po), "f"(v.x*ex), "f"(v.y*ex), "f"(v.z*ex), "f"(v.w*ex)
        : "memory");
}

// ---- K4: normalize by denom ----
__global__ void k_norm(float* __restrict__ out){
    int i = blockIdx.x*blockDim.x + threadIdx.x;   // NN*NF exact
    out[i] = out[i] / g_denom[i >> 7];
}

extern "C" void kernel_launch(void* const* d_in, const int* in_sizes, int n_in,
                              void* d_out, int out_size){
    const float* x  = (const float*)d_in[0];
    const int*   ei = (const int*)d_in[1];
    const float* ea = (const float*)d_in[2];
    // d_in[3]=node_mask, d_in[4]=edge_mask: all-valid, unused
    const float* W  = (const float*)d_in[5];
    const float* a  = (const float*)d_in[6];
    float* out = (float*)d_out;

    const int SMEM = (NF*NF + NF*68) * (int)sizeof(float);   // ~98 KB
    cudaFuncSetAttribute(k_gemm, cudaFuncAttributeMaxDynamicSharedMemorySize, SMEM);

    k_init   <<< (NN*NF)/256, 256 >>>(out);
    k_gemm   <<< NN/64, 256, SMEM >>>(x, W);
    k_proj   <<< NN/4, 128 >>>(a);
    k_logits <<< MM/256, 256 >>>(ei, ea, a);
    k_scatter<<< MM/8, 256 >>>(ei, out);
    k_norm   <<< (NN*NF)/256, 256 >>>(out);
}

// round 2
// speedup vs baseline: 1.2240x; 1.2240x over previous
#include <cuda_runtime.h>

#define NF 128                  // in/out features
#define ED 16                   // edge attr dim
#define NB 16                   // batch
#define SB 1024                 // nodes per batch (S)
#define EB 8192                 // edges per batch (E)
#define NN (NB*SB)              // 16384 total nodes
#define BE (NB*EB)              // 131072 directed input edges

// ---- scratch (device globals; no allocation allowed) ----
__device__ float g_xt[(size_t)NN*NF];   // x @ W   (8 MB)
__device__ float g_s1[NN];
__device__ float g_s2[NN];
__device__ float g_denom[NN];

// ---- K1: xt = x @ W, fused s1/s2 projection + denom zeroing ----
// 64-row tiles, 256 threads, 4x8 register micro-tile.
__global__ __launch_bounds__(256) void k_gemm(const float* __restrict__ x,
                                              const float* __restrict__ W,
                                              const float* __restrict__ a){
    extern __shared__ float sm[];
    float* Wsm = sm;              // [128][128]
    float* Xsm = sm + NF*NF;      // [128][68]  k-major (transposed x tile), padded
    const int XS = 68;
    int tid  = threadIdx.x;
    int row0 = blockIdx.x * 64;

    if (tid < 64) g_denom[row0 + tid] = 0.f;

    // stage W (16384 floats)
    const float4* W4 = (const float4*)W;
    float4* Wsm4 = (float4*)Wsm;
    #pragma unroll
    for (int i = tid; i < NF*NF/4; i += 256) Wsm4[i] = W4[i];

    // stage x tile transposed: Xsm[k][r]
    for (int i = tid; i < 64*32; i += 256){
        int r = i >> 5, c4 = (i & 31) << 2;
        float4 v = ((const float4*)(x + (size_t)(row0 + r)*NF))[i & 31];
        Xsm[(c4+0)*XS + r] = v.x;
        Xsm[(c4+1)*XS + r] = v.y;
        Xsm[(c4+2)*XS + r] = v.z;
        Xsm[(c4+3)*XS + r] = v.w;
    }
    __syncthreads();

    int tx = tid & 15;      // col group: cols 8*tx..8*tx+7
    int ty = tid >> 4;      // row group: rows 4*ty..4*ty+3
    float acc[4][8];
    #pragma unroll
    for (int i = 0; i < 4; i++)
        #pragma unroll
        for (int j = 0; j < 8; j++) acc[i][j] = 0.f;

    #pragma unroll 4
    for (int k = 0; k < NF; k++){
        float4 xv = *(const float4*)&Xsm[k*XS + 4*ty];
        float4 w0 = *(const float4*)&Wsm[k*NF + 8*tx];
        float4 w1 = *(const float4*)&Wsm[k*NF + 8*tx + 4];
        float xr[4] = {xv.x, xv.y, xv.z, xv.w};
        float wr[8] = {w0.x, w0.y, w0.z, w0.w, w1.x, w1.y, w1.z, w1.w};
        #pragma unroll
        for (int i = 0; i < 4; i++)
            #pragma unroll
            for (int j = 0; j < 8; j++)
                acc[i][j] = fmaf(xr[i], wr[j], acc[i][j]);
    }

    // store xt
    #pragma unroll
    for (int i = 0; i < 4; i++){
        size_t r = (size_t)(row0 + 4*ty + i);
        float4 o0 = {acc[i][0], acc[i][1], acc[i][2], acc[i][3]};
        float4 o1 = {acc[i][4], acc[i][5], acc[i][6], acc[i][7]};
        float4* p = (float4*)(g_xt + r*NF);
        p[2*tx]   = o0;
        p[2*tx+1] = o1;
    }

    // fused s1/s2: s1[r] = xt[r]·a[0:128], s2[r] = xt[r]·a[128:256]
    float av1[8], av2[8];
    {
        float4 t0 = __ldg((const float4*)(a + 8*tx));
        float4 t1 = __ldg((const float4*)(a + 8*tx + 4));
        float4 u0 = __ldg((const float4*)(a + NF + 8*tx));
        float4 u1 = __ldg((const float4*)(a + NF + 8*tx + 4));
        av1[0]=t0.x; av1[1]=t0.y; av1[2]=t0.z; av1[3]=t0.w;
        av1[4]=t1.x; av1[5]=t1.y; av1[6]=t1.z; av1[7]=t1.w;
        av2[0]=u0.x; av2[1]=u0.y; av2[2]=u0.z; av2[3]=u0.w;
        av2[4]=u1.x; av2[5]=u1.y; av2[6]=u1.z; av2[7]=u1.w;
    }
    #pragma unroll
    for (int i = 0; i < 4; i++){
        float p1 = 0.f, p2 = 0.f;
        #pragma unroll
        for (int j = 0; j < 8; j++){
            p1 = fmaf(acc[i][j], av1[j], p1);
            p2 = fmaf(acc[i][j], av2[j], p2);
        }
        #pragma unroll
        for (int o = 8; o; o >>= 1){   // reduce across the 16 tx lanes
            p1 += __shfl_xor_sync(0xffffffffu, p1, o);
            p2 += __shfl_xor_sync(0xffffffffu, p2, o);
        }
        if (tx == 0){
            int r = row0 + 4*ty + i;
            g_s1[r] = p1;
            g_s2[r] = p2;
        }
    }
}

// ---- K2: fused per-edge logit + exp + scatter. Warp per undirected edge
// (handles forward + reverse together); tail warps handle self-loops.
__global__ __launch_bounds__(256) void k_edge(const int* __restrict__ ei,
                                              const float* __restrict__ ea,
                                              const float* __restrict__ a,
                                              float* __restrict__ out){
    int w = (int)((blockIdx.x*blockDim.x + threadIdx.x) >> 5);
    int l = threadIdx.x & 31;
    if (w < BE){
        int base = (w >> 13) << 10;              // (w/E)*S  (E=8192, S=1024)
        int u = __ldg(&ei[2*w])   + base;
        int v = __ldg(&ei[2*w+1]) + base;
        // shared ea·a3 (lanes 0..3, float4 each)
        float p = 0.f;
        if (l < 4){
            float4 ev = __ldg(&((const float4*)(ea + (size_t)w*ED))[l]);
            float4 av = __ldg(&((const float4*)(a + 2*NF))[l]);
            p = ev.x*av.x + ev.y*av.y + ev.z*av.z + ev.w*av.w;
        }
        p += __shfl_xor_sync(0xffffffffu, p, 1);
        p += __shfl_xor_sync(0xffffffffu, p, 2);
        float t  = __shfl_sync(0xffffffffu, p, 0);
        float su = __ldg(&g_s1[u]), du = __ldg(&g_s2[u]);
        float sv = __ldg(&g_s1[v]), dv = __ldg(&g_s2[v]);
        float e1 = t + su + dv; e1 = (e1 > 0.f) ? e1 : 0.2f*e1;   // u -> v
        float e2 = t + sv + du; e2 = (e2 > 0.f) ? e2 : 0.2f*e2;   // v -> u
        float x1 = __expf(e1);
        float x2 = __expf(e2);
        if (!l){
            atomicAdd(&g_denom[v], x1);
            atomicAdd(&g_denom[u], x2);
        }
        float4 hu = __ldg(&((const float4*)(g_xt + (size_t)u*NF))[l]);
        float4 hv = __ldg(&((const float4*)(g_xt + (size_t)v*NF))[l]);
        float* pv = out + (size_t)v*NF + 4*l;
        float* pu = out + (size_t)u*NF + 4*l;
        asm volatile("red.global.add.v4.f32 [%0], {%1,%2,%3,%4};"
            :: "l"(pv), "f"(hu.x*x1), "f"(hu.y*x1), "f"(hu.z*x1), "f"(hu.w*x1)
            : "memory");
        asm volatile("red.global.add.v4.f32 [%0], {%1,%2,%3,%4};"
            :: "l"(pu), "f"(hv.x*x2), "f"(hv.y*x2), "f"(hv.z*x2), "f"(hv.w*x2)
            : "memory");
    } else {
        int n = w - BE;                          // self loop (zero edge attr)
        if (n >= NN) return;
        float e = __ldg(&g_s1[n]) + __ldg(&g_s2[n]);
        e = (e > 0.f) ? e : 0.2f*e;
        float xs = __expf(e);
        if (!l) atomicAdd(&g_denom[n], xs);
        float4 h = __ldg(&((const float4*)(g_xt + (size_t)n*NF))[l]);
        float* pn = out + (size_t)n*NF + 4*l;
        asm volatile("red.global.add.v4.f32 [%0], {%1,%2,%3,%4};"
            :: "l"(pn), "f"(h.x*xs), "f"(h.y*xs), "f"(h.z*xs), "f"(h.w*xs)
            : "memory");
    }
}

// ---- K3: normalize by denom (vectorized) ----
__global__ void k_norm(float* __restrict__ out){
    int i = blockIdx.x*blockDim.x + threadIdx.x;   // float4 index, NN*NF/4 exact
    float r = 1.f / g_denom[i >> 5];               // 32 float4 per row
    float4 v = ((float4*)out)[i];
    v.x *= r; v.y *= r; v.z *= r; v.w *= r;
    ((float4*)out)[i] = v;
}

extern "C" void kernel_launch(void* const* d_in, const int* in_sizes, int n_in,
                              void* d_out, int out_size){
    const float* x  = (const float*)d_in[0];
    const int*   ei = (const int*)d_in[1];
    const float* ea = (const float*)d_in[2];
    // d_in[3]=node_mask, d_in[4]=edge_mask: all-valid, unused
    const float* W  = (const float*)d_in[5];
    const float* a  = (const float*)d_in[6];
    float* out = (float*)d_out;

    const int SMEM = (NF*NF + NF*68) * (int)sizeof(float);   // ~98 KB
    cudaFuncSetAttribute(k_gemm, cudaFuncAttributeMaxDynamicSharedMemorySize, SMEM);

    cudaMemsetAsync(out, 0, (size_t)NN*NF*sizeof(float));
    k_gemm <<< NN/64, 256, SMEM >>>(x, W, a);
    const int NW = BE + NN;                       // warps: edge pairs + self loops
    k_edge <<< (NW*32 + 255)/256, 256 >>>(ei, ea, a, out);
    k_norm <<< (NN*NF/4)/256, 256 >>>(out);
}

// round 4
// speedup vs baseline: 1.2931x; 1.0565x over previous
#include <cuda_runtime.h>
#include <cstdint>

#define NF 128                  // in/out features
#define ED 16                   // edge attr dim
#define NB 16                   // batch
#define SB 1024                 // nodes per batch (S)
#define EB 8192                 // edges per batch (E)
#define NN (NB*SB)              // 16384 total nodes
#define BE (NB*EB)              // 131072 directed input edges

#define KC 32                   // k-chunk
#define XS 36                   // padded X smem stride

// ---- scratch (device globals; no allocation allowed) ----
__device__ float g_xt[(size_t)NN*NF];   // x @ W   (8 MB)
__device__ float g_s1[NN];
__device__ float g_s2[NN];
__device__ float g_denom[NN];

__device__ __forceinline__ void cp16(unsigned int dst, const void* src){
    asm volatile("cp.async.ca.shared.global [%0], [%1], 16;" :: "r"(dst), "l"(src));
}

// ---- K1: xt = x @ W, K-chunked + double-buffered, fused s1/s2 + denom zero ----
// 32-row tiles, 128 threads, 4x8 register micro-tile, grid = NN/32 = 512.
__global__ __launch_bounds__(128) void k_gemm(const float* __restrict__ x,
                                              const float* __restrict__ W,
                                              const float* __restrict__ a){
    __shared__ float Ws[2][KC*NF];     // 2 x 16 KB
    __shared__ float Xs[2][KC*XS];     // 2 x 4.5 KB (k-major, transposed)
    const int tid  = threadIdx.x;
    const int row0 = blockIdx.x * 32;

    if (tid < 32) g_denom[row0 + tid] = 0.f;

    const int tx = tid & 15;       // col group: cols 8*tx .. 8*tx+7
    const int ty = tid >> 4;       // row group: rows 4*ty .. 4*ty+3 (ty 0..7)

    const int xr = (tid & 127) >> 3;          // staging row  (0..15 base)
    const int xg = tid & 7;                   // staging float4 within chunk

    // ---- prologue: stage chunk 0 ----
    {
        const float4* w4 = (const float4*)W;      // chunk 0
        #pragma unroll
        for (int i = 0; i < 8; i++)
            cp16((unsigned int)__cvta_generic_to_shared(&Ws[0][(tid + i*128)*4]),
                 w4 + tid + i*128);
        asm volatile("cp.async.commit_group;");
        float4 v0 = __ldg((const float4*)(x + (size_t)(row0 + xr)*NF) + xg);
        float4 v1 = __ldg((const float4*)(x + (size_t)(row0 + xr + 16)*NF) + xg);
        #pragma unroll
        for (int j = 0; j < 4; j++){
            Xs[0][(4*xg + j)*XS + xr]      = ((const float*)&v0)[j];
            Xs[0][(4*xg + j)*XS + xr + 16] = ((const float*)&v1)[j];
        }
        asm volatile("cp.async.wait_group 0;");
        __syncthreads();
    }

    float acc[4][8];
    #pragma unroll
    for (int i = 0; i < 4; i++)
        #pragma unroll
        for (int j = 0; j < 8; j++) acc[i][j] = 0.f;

    #pragma unroll
    for (int c = 0; c < NF/KC; c++){
        const int p = c & 1;
        float4 v0, v1;
        if (c < NF/KC - 1){
            const float4* w4 = (const float4*)(W + (size_t)(c+1)*KC*NF);
            #pragma unroll
            for (int i = 0; i < 8; i++)
                cp16((unsigned int)__cvta_generic_to_shared(&Ws[1-p][(tid + i*128)*4]),
                     w4 + tid + i*128);
            asm volatile("cp.async.commit_group;");
            v0 = __ldg((const float4*)(x + (size_t)(row0 + xr)*NF + (c+1)*KC) + xg);
            v1 = __ldg((const float4*)(x + (size_t)(row0 + xr + 16)*NF + (c+1)*KC) + xg);
        }
        #pragma unroll
        for (int k = 0; k < KC; k++){
            float4 xv = *(const float4*)&Xs[p][k*XS + 4*ty];
            float4 w0 = *(const float4*)&Ws[p][k*NF + 8*tx];
            float4 w1 = *(const float4*)&Ws[p][k*NF + 8*tx + 4];
            float xrg[4] = {xv.x, xv.y, xv.z, xv.w};
            float wrg[8] = {w0.x, w0.y, w0.z, w0.w, w1.x, w1.y, w1.z, w1.w};
            #pragma unroll
            for (int i = 0; i < 4; i++)
                #pragma unroll
                for (int j = 0; j < 8; j++)
                    acc[i][j] = fmaf(xrg[i], wrg[j], acc[i][j]);
        }
        if (c < NF/KC - 1){
            #pragma unroll
            for (int j = 0; j < 4; j++){
                Xs[1-p][(4*xg + j)*XS + xr]      = ((const float*)&v0)[j];
                Xs[1-p][(4*xg + j)*XS + xr + 16] = ((const float*)&v1)[j];
            }
            asm volatile("cp.async.wait_group 0;");
        }
        __syncthreads();
    }

    // store xt
    #pragma unroll
    for (int i = 0; i < 4; i++){
        size_t r = (size_t)(row0 + 4*ty + i);
        float4 o0 = {acc[i][0], acc[i][1], acc[i][2], acc[i][3]};
        float4 o1 = {acc[i][4], acc[i][5], acc[i][6], acc[i][7]};
        float4* ptr = (float4*)(g_xt + r*NF);
        ptr[2*tx]   = o0;
        ptr[2*tx+1] = o1;
    }

    // fused s1/s2: s1[r] = xt[r]·a[0:128], s2[r] = xt[r]·a[128:256]
    float av1[8], av2[8];
    {
        float4 t0 = __ldg((const float4*)(a + 8*tx));
        float4 t1 = __ldg((const float4*)(a + 8*tx + 4));
        float4 u0 = __ldg((const float4*)(a + NF + 8*tx));
        float4 u1 = __ldg((const float4*)(a + NF + 8*tx + 4));
        av1[0]=t0.x; av1[1]=t0.y; av1[2]=t0.z; av1[3]=t0.w;
        av1[4]=t1.x; av1[5]=t1.y; av1[6]=t1.z; av1[7]=t1.w;
        av2[0]=u0.x; av2[1]=u0.y; av2[2]=u0.z; av2[3]=u0.w;
        av2[4]=u1.x; av2[5]=u1.y; av2[6]=u1.z; av2[7]=u1.w;
    }
    #pragma unroll
    for (int i = 0; i < 4; i++){
        float p1 = 0.f, p2 = 0.f;
        #pragma unroll
        for (int j = 0; j < 8; j++){
            p1 = fmaf(acc[i][j], av1[j], p1);
            p2 = fmaf(acc[i][j], av2[j], p2);
        }
        #pragma unroll
        for (int o = 8; o; o >>= 1){     // reduce across the 16 tx lanes
            p1 += __shfl_xor_sync(0xffffffffu, p1, o);
            p2 += __shfl_xor_sync(0xffffffffu, p2, o);
        }
        if (tx == 0){
            int r = row0 + 4*ty + i;
            g_s1[r] = p1;
            g_s2[r] = p2;
        }
    }
}

// ---- K2: fused per-edge logit + exp + scatter. Warp per undirected edge
// (handles forward + reverse together); tail warps handle self-loops.
__global__ __launch_bounds__(256) void k_edge(const int* __restrict__ ei,
                                              const float* __restrict__ ea,
                                              const float* __restrict__ a,
                                              float* __restrict__ out){
    int w = (int)((blockIdx.x*blockDim.x + threadIdx.x) >> 5);
    int l = threadIdx.x & 31;
    if (w < BE){
        int base = (w >> 13) << 10;              // (w/E)*S  (E=8192, S=1024)
        int u = __ldg(&ei[2*w])   + base;
        int v = __ldg(&ei[2*w+1]) + base;
        // issue the big gathers early — independent of the logit math
        float4 hu = __ldg(&((const float4*)(g_xt + (size_t)u*NF))[l]);
        float4 hv = __ldg(&((const float4*)(g_xt + (size_t)v*NF))[l]);
        // shared ea·a3 (lanes 0..3, float4 each)
        float p = 0.f;
        if (l < 4){
            float4 ev = __ldg(&((const float4*)(ea + (size_t)w*ED))[l]);
            float4 av = __ldg(&((const float4*)(a + 2*NF))[l]);
            p = ev.x*av.x + ev.y*av.y + ev.z*av.z + ev.w*av.w;
        }
        p += __shfl_xor_sync(0xffffffffu, p, 1);
        p += __shfl_xor_sync(0xffffffffu, p, 2);
        float t  = __shfl_sync(0xffffffffu, p, 0);
        float su = __ldg(&g_s1[u]), du = __ldg(&g_s2[u]);
        float sv = __ldg(&g_s1[v]), dv = __ldg(&g_s2[v]);
        float e1 = t + su + dv; e1 = (e1 > 0.f) ? e1 : 0.2f*e1;   // u -> v
        float e2 = t + sv + du; e2 = (e2 > 0.f) ? e2 : 0.2f*e2;   // v -> u
        float x1 = __expf(e1);
        float x2 = __expf(e2);
        if (!l){
            atomicAdd(&g_denom[v], x1);
            atomicAdd(&g_denom[u], x2);
        }
        float* pv = out + (size_t)v*NF + 4*l;
        float* pu = out + (size_t)u*NF + 4*l;
        asm volatile("red.global.add.v4.f32 [%0], {%1,%2,%3,%4};"
            :: "l"(pv), "f"(hu.x*x1), "f"(hu.y*x1), "f"(hu.z*x1), "f"(hu.w*x1)
            : "memory");
        asm volatile("red.global.add.v4.f32 [%0], {%1,%2,%3,%4};"
            :: "l"(pu), "f"(hv.x*x2), "f"(hv.y*x2), "f"(hv.z*x2), "f"(hv.w*x2)
            : "memory");
    } else {
        int n = w - BE;                          // self loop (zero edge attr)
        if (n >= NN) return;
        float4 h = __ldg(&((const float4*)(g_xt + (size_t)n*NF))[l]);
        float e = __ldg(&g_s1[n]) + __ldg(&g_s2[n]);
        e = (e > 0.f) ? e : 0.2f*e;
        float xs = __expf(e);
        if (!l) atomicAdd(&g_denom[n], xs);
        float* pn = out + (size_t)n*NF + 4*l;
        asm volatile("red.global.add.v4.f32 [%0], {%1,%2,%3,%4};"
            :: "l"(pn), "f"(h.x*xs), "f"(h.y*xs), "f"(h.z*xs), "f"(h.w*xs)
            : "memory");
    }
}

// ---- K3: normalize by denom (vectorized) ----
__global__ void k_norm(float* __restrict__ out){
    int i = blockIdx.x*blockDim.x + threadIdx.x;   // float4 index, NN*NF/4 exact
    float r = 1.f / g_denom[i >> 5];               // 32 float4 per row
    float4 v = ((float4*)out)[i];
    v.x *= r; v.y *= r; v.z *= r; v.w *= r;
    ((float4*)out)[i] = v;
}

extern "C" void kernel_launch(void* const* d_in, const int* in_sizes, int n_in,
                              void* d_out, int out_size){
    const float* x  = (const float*)d_in[0];
    const int*   ei = (const int*)d_in[1];
    const float* ea = (const float*)d_in[2];
    // d_in[3]=node_mask, d_in[4]=edge_mask: all-valid, unused
    const float* W  = (const float*)d_in[5];
    const float* a  = (const float*)d_in[6];
    float* out = (float*)d_out;

    cudaMemsetAsync(out, 0, (size_t)NN*NF*sizeof(float));
    k_gemm <<< NN/32, 128 >>>(x, W, a);
    const int NW = BE + NN;                       // warps: edge pairs + self loops
    k_edge <<< (NW*32 + 255)/256, 256 >>>(ei, ea, a, out);
    k_norm <<< (NN*NF/4)/256, 256 >>>(out);
}

// round 5
// speedup vs baseline: 1.4822x; 1.1462x over previous
#include <cuda_runtime.h>
#include <cstdint>

#define NF 128                  // in/out features
#define ED 16                   // edge attr dim
#define NB 16                   // batch
#define SB 1024                 // nodes per batch (S)
#define EB 8192                 // edges per batch (E)
#define NN (NB*SB)              // 16384 total nodes
#define BE (NB*EB)              // 131072 directed input edges

#define KC 32                   // k-chunk
#define XS 68                   // padded X smem stride (rows fast dim)

// ---- scratch (device globals; no allocation allowed) ----
__device__ float g_xt[(size_t)NN*NF];   // x @ W   (8 MB)
__device__ float g_s1[NN];
__device__ float g_s2[NN];
__device__ float g_denom[NN];

__device__ __forceinline__ void cp16(unsigned int dst, const void* src){
    asm volatile("cp.async.ca.shared.global [%0], [%1], 16;" :: "r"(dst), "l"(src));
}
__device__ __forceinline__ unsigned long long packdup(float w){
    unsigned long long r;
    unsigned int u = __float_as_uint(w);
    asm("mov.b64 %0, {%1, %2};" : "=l"(r) : "r"(u), "r"(u));
    return r;
}
__device__ __forceinline__ void fma2(unsigned long long& d,
                                     unsigned long long a, unsigned long long b){
    asm("fma.rn.f32x2 %0, %1, %2, %0;" : "+l"(d) : "l"(a), "l"(b));
}

// ---- K1: xt = x @ W. 64-row tiles, 128 threads, 8x8 micro-tile via f32x2,
// K-chunked + cp.async double-buffered. Fused s1/s2 + denom zeroing.
__global__ __launch_bounds__(128) void k_gemm(const float* __restrict__ x,
                                              const float* __restrict__ W,
                                              const float* __restrict__ a){
    __shared__ float Ws[2][KC*NF];     // 2 x 16 KB
    __shared__ float Xs[2][KC*XS];     // 2 x 8.5 KB (k-major: Xs[k][row])
    const int tid  = threadIdx.x;
    const int row0 = blockIdx.x * 64;

    if (tid < 64) g_denom[row0 + tid] = 0.f;

    const int tx = tid & 15;       // col group: cols 8*tx .. 8*tx+7
    const int ty = tid >> 4;       // row group: rows 8*ty .. 8*ty+7 (ty 0..7)

    // X staging map: 4 float4 per thread; idx = tid + t*128 -> row, g(float4 in chunk)
    int srow[4], sg[4];
    #pragma unroll
    for (int t = 0; t < 4; t++){ int idx = tid + t*128; srow[t] = idx >> 3; sg[t] = idx & 7; }

    // ---- prologue: stage chunk 0 ----
    {
        const float4* w4 = (const float4*)W;
        #pragma unroll
        for (int i = 0; i < 8; i++)
            cp16((unsigned int)__cvta_generic_to_shared(&Ws[0][(tid + i*128)*4]),
                 w4 + tid + i*128);
        asm volatile("cp.async.commit_group;");
        #pragma unroll
        for (int t = 0; t < 4; t++){
            float4 v = __ldg((const float4*)(x + (size_t)(row0 + srow[t])*NF) + sg[t]);
            #pragma unroll
            for (int j = 0; j < 4; j++)
                Xs[0][(4*sg[t] + j)*XS + srow[t]] = ((const float*)&v)[j];
        }
        asm volatile("cp.async.wait_group 0;");
        __syncthreads();
    }

    unsigned long long acc2[4][8];     // row-pairs (8ty+2i, 8ty+2i+1) x cols 8tx+j
    #pragma unroll
    for (int i = 0; i < 4; i++)
        #pragma unroll
        for (int j = 0; j < 8; j++) acc2[i][j] = 0ULL;

    #pragma unroll 1
    for (int c = 0; c < NF/KC; c++){
        const int p = c & 1;
        float4 v[4];
        if (c < NF/KC - 1){
            const float4* w4 = (const float4*)(W + (size_t)(c+1)*KC*NF);
            #pragma unroll
            for (int i = 0; i < 8; i++)
                cp16((unsigned int)__cvta_generic_to_shared(&Ws[1-p][(tid + i*128)*4]),
                     w4 + tid + i*128);
            asm volatile("cp.async.commit_group;");
            #pragma unroll
            for (int t = 0; t < 4; t++)
                v[t] = __ldg((const float4*)(x + (size_t)(row0 + srow[t])*NF + (c+1)*KC) + sg[t]);
        }
        #pragma unroll
        for (int k = 0; k < KC; k++){
            // 8 row values for this thread = 4 packed f32x2 pairs (free reinterpret)
            longlong2 xA = *(const longlong2*)&Xs[p][k*XS + 8*ty];
            longlong2 xB = *(const longlong2*)&Xs[p][k*XS + 8*ty + 4];
            unsigned long long xp[4] = {(unsigned long long)xA.x, (unsigned long long)xA.y,
                                        (unsigned long long)xB.x, (unsigned long long)xB.y};
            float4 w0 = *(const float4*)&Ws[p][k*NF + 8*tx];
            float4 w1 = *(const float4*)&Ws[p][k*NF + 8*tx + 4];
            unsigned long long wp[8];
            wp[0]=packdup(w0.x); wp[1]=packdup(w0.y); wp[2]=packdup(w0.z); wp[3]=packdup(w0.w);
            wp[4]=packdup(w1.x); wp[5]=packdup(w1.y); wp[6]=packdup(w1.z); wp[7]=packdup(w1.w);
            #pragma unroll
            for (int i = 0; i < 4; i++)
                #pragma unroll
                for (int j = 0; j < 8; j++)
                    fma2(acc2[i][j], xp[i], wp[j]);
        }
        if (c < NF/KC - 1){
            #pragma unroll
            for (int t = 0; t < 4; t++)
                #pragma unroll
                for (int j = 0; j < 4; j++)
                    Xs[1-p][(4*sg[t] + j)*XS + srow[t]] = ((const float*)&v[t])[j];
            asm volatile("cp.async.wait_group 0;");
        }
        __syncthreads();
    }

    // unpack: accf[local row 0..7][col 0..7]
    float accf[8][8];
    #pragma unroll
    for (int i = 0; i < 4; i++)
        #pragma unroll
        for (int j = 0; j < 8; j++){
            unsigned int lo, hi;
            asm("mov.b64 {%0, %1}, %2;" : "=r"(lo), "=r"(hi) : "l"(acc2[i][j]));
            accf[2*i][j]   = __uint_as_float(lo);
            accf[2*i+1][j] = __uint_as_float(hi);
        }

    // store xt
    #pragma unroll
    for (int i = 0; i < 8; i++){
        size_t r = (size_t)(row0 + 8*ty + i);
        float4 o0 = {accf[i][0], accf[i][1], accf[i][2], accf[i][3]};
        float4 o1 = {accf[i][4], accf[i][5], accf[i][6], accf[i][7]};
        float4* ptr = (float4*)(g_xt + r*NF);
        ptr[2*tx]   = o0;
        ptr[2*tx+1] = o1;
    }

    // fused s1/s2: s1[r] = xt[r]·a[0:128], s2[r] = xt[r]·a[128:256]
    float av1[8], av2[8];
    {
        float4 t0 = __ldg((const float4*)(a + 8*tx));
        float4 t1 = __ldg((const float4*)(a + 8*tx + 4));
        float4 u0 = __ldg((const float4*)(a + NF + 8*tx));
        float4 u1 = __ldg((const float4*)(a + NF + 8*tx + 4));
        av1[0]=t0.x; av1[1]=t0.y; av1[2]=t0.z; av1[3]=t0.w;
        av1[4]=t1.x; av1[5]=t1.y; av1[6]=t1.z; av1[7]=t1.w;
        av2[0]=u0.x; av2[1]=u0.y; av2[2]=u0.z; av2[3]=u0.w;
        av2[4]=u1.x; av2[5]=u1.y; av2[6]=u1.z; av2[7]=u1.w;
    }
    #pragma unroll
    for (int i = 0; i < 8; i++){
        float p1 = 0.f, p2 = 0.f;
        #pragma unroll
        for (int j = 0; j < 8; j++){
            p1 = fmaf(accf[i][j], av1[j], p1);
            p2 = fmaf(accf[i][j], av2[j], p2);
        }
        #pragma unroll
        for (int o = 8; o; o >>= 1){     // reduce across the 16 tx lanes
            p1 += __shfl_xor_sync(0xffffffffu, p1, o);
            p2 += __shfl_xor_sync(0xffffffffu, p2, o);
        }
        if (tx == 0){
            int r = row0 + 8*ty + i;
            g_s1[r] = p1;
            g_s2[r] = p2;
        }
    }
}

// ---- K2: fused per-edge logit + exp + scatter. Warp per undirected edge
// (handles forward + reverse together); tail warps handle self-loops.
__global__ __launch_bounds__(256) void k_edge(const int* __restrict__ ei,
                                              const float* __restrict__ ea,
                                              const float* __restrict__ a,
                                              float* __restrict__ out){
    int w = (int)((blockIdx.x*blockDim.x + threadIdx.x) >> 5);
    int l = threadIdx.x & 31;
    if (w < BE){
        int base = (w >> 13) << 10;              // (w/E)*S  (E=8192, S=1024)
        int u = __ldg(&ei[2*w])   + base;
        int v = __ldg(&ei[2*w+1]) + base;
        // issue the big gathers early — independent of the logit math
        float4 hu = __ldg(&((const float4*)(g_xt + (size_t)u*NF))[l]);
        float4 hv = __ldg(&((const float4*)(g_xt + (size_t)v*NF))[l]);
        // shared ea·a3 (lanes 0..3, float4 each)
        float p = 0.f;
        if (l < 4){
            float4 ev = __ldg(&((const float4*)(ea + (size_t)w*ED))[l]);
            float4 av = __ldg(&((const float4*)(a + 2*NF))[l]);
            p = ev.x*av.x + ev.y*av.y + ev.z*av.z + ev.w*av.w;
        }
        p += __shfl_xor_sync(0xffffffffu, p, 1);
        p += __shfl_xor_sync(0xffffffffu, p, 2);
        float t  = __shfl_sync(0xffffffffu, p, 0);
        float su = __ldg(&g_s1[u]), du = __ldg(&g_s2[u]);
        float sv = __ldg(&g_s1[v]), dv = __ldg(&g_s2[v]);
        float e1 = t + su + dv; e1 = (e1 > 0.f) ? e1 : 0.2f*e1;   // u -> v
        float e2 = t + sv + du; e2 = (e2 > 0.f) ? e2 : 0.2f*e2;   // v -> u
        float x1 = __expf(e1);
        float x2 = __expf(e2);
        if (!l){
            atomicAdd(&g_denom[v], x1);
            atomicAdd(&g_denom[u], x2);
        }
        float* pv = out + (size_t)v*NF + 4*l;
        float* pu = out + (size_t)u*NF + 4*l;
        asm volatile("red.global.add.v4.f32 [%0], {%1,%2,%3,%4};"
            :: "l"(pv), "f"(hu.x*x1), "f"(hu.y*x1), "f"(hu.z*x1), "f"(hu.w*x1)
            : "memory");
        asm volatile("red.global.add.v4.f32 [%0], {%1,%2,%3,%4};"
            :: "l"(pu), "f"(hv.x*x2), "f"(hv.y*x2), "f"(hv.z*x2), "f"(hv.w*x2)
            : "memory");
    } else {
        int n = w - BE;                          // self loop (zero edge attr)
        if (n >= NN) return;
        float4 h = __ldg(&((const float4*)(g_xt + (size_t)n*NF))[l]);
        float e = __ldg(&g_s1[n]) + __ldg(&g_s2[n]);
        e = (e > 0.f) ? e : 0.2f*e;
        float xs = __expf(e);
        if (!l) atomicAdd(&g_denom[n], xs);
        float* pn = out + (size_t)n*NF + 4*l;
        asm volatile("red.global.add.v4.f32 [%0], {%1,%2,%3,%4};"
            :: "l"(pn), "f"(h.x*xs), "f"(h.y*xs), "f"(h.z*xs), "f"(h.w*xs)
            : "memory");
    }
}

// ---- K3: normalize by denom (vectorized) ----
__global__ void k_norm(float* __restrict__ out){
    int i = blockIdx.x*blockDim.x + threadIdx.x;   // float4 index, NN*NF/4 exact
    float r = 1.f / g_denom[i >> 5];               // 32 float4 per row
    float4 v = ((float4*)out)[i];
    v.x *= r; v.y *= r; v.z *= r; v.w *= r;
    ((float4*)out)[i] = v;
}

extern "C" void kernel_launch(void* const* d_in, const int* in_sizes, int n_in,
                              void* d_out, int out_size){
    const float* x  = (const float*)d_in[0];
    const int*   ei = (const int*)d_in[1];
    const float* ea = (const float*)d_in[2];
    // d_in[3]=node_mask, d_in[4]=edge_mask: all-valid, unused
    const float* W  = (const float*)d_in[5];
    const float* a  = (const float*)d_in[6];
    float* out = (float*)d_out;

    cudaMemsetAsync(out, 0, (size_t)NN*NF*sizeof(float));
    k_gemm <<< NN/64, 128 >>>(x, W, a);
    const int NW = BE + NN;                       // warps: edge pairs + self loops
    k_edge <<< (NW*32 + 255)/256, 256 >>>(ei, ea, a, out);
    k_norm <<< (NN*NF/4)/256, 256 >>>(out);
}

// round 6
// speedup vs baseline: 1.4925x; 1.0069x over previous
#include <cuda_runtime.h>
#include <cstdint>

#define NF 128                  // in/out features
#define ED 16                   // edge attr dim
#define NB 16                   // batch
#define SB 1024                 // nodes per batch (S)
#define EB 8192                 // edges per batch (E)
#define NN (NB*SB)              // 16384 total nodes
#define BE (NB*EB)              // 131072 directed input edges

#define KC 32                   // k-chunk
#define XS 36                   // padded X smem stride (rows fast dim)

// ---- scratch (device globals; no allocation allowed) ----
__device__ float g_xt[(size_t)NN*NF];   // x @ W   (8 MB)
__device__ float g_s1[NN];
__device__ float g_s2[NN];
__device__ float g_denom[NN];

__device__ __forceinline__ void cp16(unsigned int dst, const void* src){
    asm volatile("cp.async.ca.shared.global [%0], [%1], 16;" :: "r"(dst), "l"(src));
}
__device__ __forceinline__ unsigned long long packdup(float w){
    unsigned long long r;
    unsigned int u = __float_as_uint(w);
    asm("mov.b64 %0, {%1, %2};" : "=l"(r) : "r"(u), "r"(u));
    return r;
}
__device__ __forceinline__ void fma2(unsigned long long& d,
                                     unsigned long long a, unsigned long long b){
    asm("fma.rn.f32x2 %0, %1, %2, %0;" : "+l"(d) : "l"(a), "l"(b));
}

// ---- K1: xt = x @ W. 32-row tiles, 128 threads, 8x4 micro-tile via f32x2,
// K-chunked + cp.async double-buffered. Fused s1/s2 + denom zeroing. grid=512.
__global__ __launch_bounds__(128) void k_gemm(const float* __restrict__ x,
                                              const float* __restrict__ W,
                                              const float* __restrict__ a){
    __shared__ float Ws[2][KC*NF];     // 2 x 16 KB
    __shared__ float Xs[2][KC*XS];     // 2 x 4.5 KB (k-major: Xs[k][row])
    const int tid  = threadIdx.x;
    const int row0 = blockIdx.x * 32;

    if (tid < 32) g_denom[row0 + tid] = 0.f;

    const int tx = tid & 31;       // col group: cols 4*tx .. 4*tx+3
    const int ty = tid >> 5;       // row group: rows 8*ty .. 8*ty+7 (ty 0..3)

    // X staging: 32 rows x KC floats = 256 float4; 2 per thread
    int srow[2], sg[2];
    #pragma unroll
    for (int t = 0; t < 2; t++){ int idx = tid + t*128; srow[t] = idx >> 3; sg[t] = idx & 7; }

    // ---- prologue: stage chunk 0 ----
    {
        const float4* w4 = (const float4*)W;
        #pragma unroll
        for (int i = 0; i < 8; i++)
            cp16((unsigned int)__cvta_generic_to_shared(&Ws[0][(tid + i*128)*4]),
                 w4 + tid + i*128);
        asm volatile("cp.async.commit_group;");
        #pragma unroll
        for (int t = 0; t < 2; t++){
            float4 v = __ldg((const float4*)(x + (size_t)(row0 + srow[t])*NF) + sg[t]);
            #pragma unroll
            for (int j = 0; j < 4; j++)
                Xs[0][(4*sg[t] + j)*XS + srow[t]] = ((const float*)&v)[j];
        }
        asm volatile("cp.async.wait_group 0;");
        __syncthreads();
    }

    unsigned long long acc2[4][4];     // row-pairs (8ty+2i, 8ty+2i+1) x cols 4tx+j
    #pragma unroll
    for (int i = 0; i < 4; i++)
        #pragma unroll
        for (int j = 0; j < 4; j++) acc2[i][j] = 0ULL;

    #pragma unroll 1
    for (int c = 0; c < NF/KC; c++){
        const int p = c & 1;
        float4 v[2];
        if (c < NF/KC - 1){
            const float4* w4 = (const float4*)(W + (size_t)(c+1)*KC*NF);
            #pragma unroll
            for (int i = 0; i < 8; i++)
                cp16((unsigned int)__cvta_generic_to_shared(&Ws[1-p][(tid + i*128)*4]),
                     w4 + tid + i*128);
            asm volatile("cp.async.commit_group;");
            #pragma unroll
            for (int t = 0; t < 2; t++)
                v[t] = __ldg((const float4*)(x + (size_t)(row0 + srow[t])*NF + (c+1)*KC) + sg[t]);
        }
        #pragma unroll
        for (int k = 0; k < KC; k++){
            // 8 row values for this thread = 4 packed f32x2 pairs (free reinterpret,
            // broadcast within warp since all lanes share ty)
            longlong2 xA = *(const longlong2*)&Xs[p][k*XS + 8*ty];
            longlong2 xB = *(const longlong2*)&Xs[p][k*XS + 8*ty + 4];
            unsigned long long xp[4] = {(unsigned long long)xA.x, (unsigned long long)xA.y,
                                        (unsigned long long)xB.x, (unsigned long long)xB.y};
            float4 w0 = *(const float4*)&Ws[p][k*NF + 4*tx];
            unsigned long long wp[4];
            wp[0]=packdup(w0.x); wp[1]=packdup(w0.y); wp[2]=packdup(w0.z); wp[3]=packdup(w0.w);
            #pragma unroll
            for (int i = 0; i < 4; i++)
                #pragma unroll
                for (int j = 0; j < 4; j++)
                    fma2(acc2[i][j], xp[i], wp[j]);
        }
        if (c < NF/KC - 1){
            #pragma unroll
            for (int t = 0; t < 2; t++)
                #pragma unroll
                for (int j = 0; j < 4; j++)
                    Xs[1-p][(4*sg[t] + j)*XS + srow[t]] = ((const float*)&v[t])[j];
            asm volatile("cp.async.wait_group 0;");
        }
        __syncthreads();
    }

    // unpack: accf[local row 0..7][col 0..3]
    float accf[8][4];
    #pragma unroll
    for (int i = 0; i < 4; i++)
        #pragma unroll
        for (int j = 0; j < 4; j++){
            unsigned int lo, hi;
            asm("mov.b64 {%0, %1}, %2;" : "=r"(lo), "=r"(hi) : "l"(acc2[i][j]));
            accf[2*i][j]   = __uint_as_float(lo);
            accf[2*i+1][j] = __uint_as_float(hi);
        }

    // store xt (lanes tx: 32 consecutive float4 per row = contiguous 512B)
    #pragma unroll
    for (int i = 0; i < 8; i++){
        size_t r = (size_t)(row0 + 8*ty + i);
        float4 o = {accf[i][0], accf[i][1], accf[i][2], accf[i][3]};
        ((float4*)(g_xt + r*NF))[tx] = o;
    }

    // fused s1/s2: s1[r] = xt[r]·a[0:128], s2[r] = xt[r]·a[128:256]
    float av1[4], av2[4];
    {
        float4 t0 = __ldg((const float4*)(a + 4*tx));
        float4 u0 = __ldg((const float4*)(a + NF + 4*tx));
        av1[0]=t0.x; av1[1]=t0.y; av1[2]=t0.z; av1[3]=t0.w;
        av2[0]=u0.x; av2[1]=u0.y; av2[2]=u0.z; av2[3]=u0.w;
    }
    #pragma unroll
    for (int i = 0; i < 8; i++){
        float p1 = 0.f, p2 = 0.f;
        #pragma unroll
        for (int j = 0; j < 4; j++){
            p1 = fmaf(accf[i][j], av1[j], p1);
            p2 = fmaf(accf[i][j], av2[j], p2);
        }
        #pragma unroll
        for (int o = 16; o; o >>= 1){    // reduce across full warp (32 tx lanes)
            p1 += __shfl_xor_sync(0xffffffffu, p1, o);
            p2 += __shfl_xor_sync(0xffffffffu, p2, o);
        }
        if (tx == 0){
            int r = row0 + 8*ty + i;
            g_s1[r] = p1;
            g_s2[r] = p2;
        }
    }
}

// ---- K2: fused per-edge logit + exp + scatter. Warp per undirected edge
// (handles forward + reverse together); tail warps handle self-loops.
__global__ __launch_bounds__(256) void k_edge(const int* __restrict__ ei,
                                              const float* __restrict__ ea,
                                              const float* __restrict__ a,
                                              float* __restrict__ out){
    int w = (int)((blockIdx.x*blockDim.x + threadIdx.x) >> 5);
    int l = threadIdx.x & 31;
    if (w < BE){
        int base = (w >> 13) << 10;              // (w/E)*S  (E=8192, S=1024)
        int u = __ldg(&ei[2*w])   + base;
        int v = __ldg(&ei[2*w+1]) + base;
        // issue the big gathers early — independent of the logit math
        float4 hu = __ldg(&((const float4*)(g_xt + (size_t)u*NF))[l]);
        float4 hv = __ldg(&((const float4*)(g_xt + (size_t)v*NF))[l]);
        // shared ea·a3 (lanes 0..3, float4 each)
        float p = 0.f;
        if (l < 4){
            float4 ev = __ldg(&((const float4*)(ea + (size_t)w*ED))[l]);
            float4 av = __ldg(&((const float4*)(a + 2*NF))[l]);
            p = ev.x*av.x + ev.y*av.y + ev.z*av.z + ev.w*av.w;
        }
        p += __shfl_xor_sync(0xffffffffu, p, 1);
        p += __shfl_xor_sync(0xffffffffu, p, 2);
        float t  = __shfl_sync(0xffffffffu, p, 0);
        float su = __ldg(&g_s1[u]), du = __ldg(&g_s2[u]);
        float sv = __ldg(&g_s1[v]), dv = __ldg(&g_s2[v]);
        float e1 = t + su + dv; e1 = (e1 > 0.f) ? e1 : 0.2f*e1;   // u -> v
        float e2 = t + sv + du; e2 = (e2 > 0.f) ? e2 : 0.2f*e2;   // v -> u
        float x1 = __expf(e1);
        float x2 = __expf(e2);
        if (!l){
            atomicAdd(&g_denom[v], x1);
            atomicAdd(&g_denom[u], x2);
        }
        float* pv = out + (size_t)v*NF + 4*l;
        float* pu = out + (size_t)u*NF + 4*l;
        asm volatile("red.global.add.v4.f32 [%0], {%1,%2,%3,%4};"
            :: "l"(pv), "f"(hu.x*x1), "f"(hu.y*x1), "f"(hu.z*x1), "f"(hu.w*x1)
            : "memory");
        asm volatile("red.global.add.v4.f32 [%0], {%1,%2,%3,%4};"
            :: "l"(pu), "f"(hv.x*x2), "f"(hv.y*x2), "f"(hv.z*x2), "f"(hv.w*x2)
            : "memory");
    } else {
        int n = w - BE;                          // self loop (zero edge attr)
        if (n >= NN) return;
        float4 h = __ldg(&((const float4*)(g_xt + (size_t)n*NF))[l]);
        float e = __ldg(&g_s1[n]) + __ldg(&g_s2[n]);
        e = (e > 0.f) ? e : 0.2f*e;
        float xs = __expf(e);
        if (!l) atomicAdd(&g_denom[n], xs);
        float* pn = out + (size_t)n*NF + 4*l;
        asm volatile("red.global.add.v4.f32 [%0], {%1,%2,%3,%4};"
            :: "l"(pn), "f"(h.x*xs), "f"(h.y*xs), "f"(h.z*xs), "f"(h.w*xs)
            : "memory");
    }
}

// ---- K3: normalize by denom (vectorized) ----
__global__ void k_norm(float* __restrict__ out){
    int i = blockIdx.x*blockDim.x + threadIdx.x;   // float4 index, NN*NF/4 exact
    float r = 1.f / g_denom[i >> 5];               // 32 float4 per row
    float4 v = ((float4*)out)[i];
    v.x *= r; v.y *= r; v.z *= r; v.w *= r;
    ((float4*)out)[i] = v;
}

extern "C" void kernel_launch(void* const* d_in, const int* in_sizes, int n_in,
                              void* d_out, int out_size){
    const float* x  = (const float*)d_in[0];
    const int*   ei = (const int*)d_in[1];
    const float* ea = (const float*)d_in[2];
    // d_in[3]=node_mask, d_in[4]=edge_mask: all-valid, unused
    const float* W  = (const float*)d_in[5];
    const float* a  = (const float*)d_in[6];
    float* out = (float*)d_out;

    cudaMemsetAsync(out, 0, (size_t)NN*NF*sizeof(float));
    k_gemm <<< NN/32, 128 >>>(x, W, a);
    const int NW = BE + NN;                       // warps: edge pairs + self loops
    k_edge <<< (NW*32 + 255)/256, 256 >>>(ei, ea, a, out);
    k_norm <<< (NN*NF/4)/256, 256 >>>(out);
}